// round 4
// baseline (speedup 1.0000x reference)
#include <cuda_runtime.h>
#include <math.h>

// ---------------- problem constants ----------------
#define BATCH 256
// conv1: in [256,3,250,250], w [6,3,5,5], s2 p1 -> [256,6,124,124]
// pool1 (fused) -> [256,6,123,123]
// conv2: w [15,6,3,3], s2 p1 -> [256,15,62,62]
// pool2 (fused) -> [256,15,61,61]  (flatten K = 15*61*61 = 55815)
#define KDIM 55815
#define KSPLIT 37
#define KCHUNK 1536

// ---------------- scratch (static device arrays; no allocation) ----------------
__device__ float g_pool1[(size_t)BATCH * 6 * 123 * 123];   // 93.0 MB
__device__ float g_pool2[(size_t)BATCH * 15 * 61 * 61];    // 57.2 MB (fc1 "A")
__device__ float g_part[(size_t)KSPLIT * BATCH * 120];     // 4.5 MB
__device__ float g_h1[BATCH * 120];
__device__ float g_feat[BATCH * 84];
__device__ float g_probs[BATCH];

// ---------------- f32x2 helpers ----------------
typedef unsigned long long ull;
__device__ __forceinline__ ull pk(float lo, float hi) {
    ull r;
    asm("mov.b64 %0, {%1, %2};" : "=l"(r) : "f"(lo), "f"(hi));
    return r;
}
__device__ __forceinline__ void ffma2(ull& d, ull a, ull b) {
    asm("fma.rn.f32x2 %0, %1, %2, %0;" : "+l"(d) : "l"(a), "l"(b));
}
__device__ __forceinline__ float2 upk(ull v) {
    float2 r;
    asm("mov.b64 {%0, %1}, %2;" : "=f"(r.x), "=f"(r.y) : "l"(v));
    return r;
}

// ---------------- conv1 + relu + fused maxpool(2,2,s1) ----------------
// block (32,4): conv tile 64(ow) x 8(oh); pool tile 63 x 7 (grid.x step 60)
// Even/odd phase-split input tiles -> conflict-free lane-stride-1 LDS.
// f32x2 over oc-pairs; per thread: 2 rows x 2 cols x 6 oc.
__global__ __launch_bounds__(128) void conv1_kernel(
    const float* __restrict__ x, const float* __restrict__ w,
    const float* __restrict__ bias)
{
    __shared__ float sE[3][19][66];   // even input cols
    __shared__ float sO[3][19][66];   // odd input cols
    __shared__ ull   sW2[3][5][5][3]; // [c][kh][kw][ocpair]
    __shared__ float sOut[6][8][65];
    const int b = blockIdx.z;
    const int ow0 = blockIdx.x * 60;
    const int oh0 = blockIdx.y * 7;
    const int tx = threadIdx.x, ty = threadIdx.y;   // 32 x 4
    const int tid = ty * 32 + tx;

    // pack weights {w[2p], w[2p+1]} per (c,kh,kw)
    for (int i = tid; i < 225; i += 128) {
        int p = i % 3;
        int kw = (i / 3) % 5;
        int kh = (i / 15) % 5;
        int c = i / 75;
        float w0 = w[(((2 * p) * 3 + c) * 5 + kh) * 5 + kw];
        float w1 = w[(((2 * p + 1) * 3 + c) * 5 + kh) * 5 + kw];
        sW2[c][kh][kw][p] = pk(w0, w1);
    }

    const int ih0 = oh0 * 2 - 1;
    const int iw0 = ow0 * 2 - 1;
    const float* xb = x + (size_t)b * 3 * 250 * 250;
    for (int i = tid; i < 3 * 19 * 131; i += 128) {
        int c = i / (19 * 131);
        int rem = i % (19 * 131);
        int r = rem / 131, col = rem % 131;
        int ih = ih0 + r, iw = iw0 + col;
        float v = 0.f;
        if (ih >= 0 && ih < 250 && iw >= 0 && iw < 250)
            v = xb[(c * 250 + ih) * 250 + iw];
        if (col & 1) sO[c][r][col >> 1] = v;
        else         sE[c][r][col >> 1] = v;
    }
    __syncthreads();

    ull acc2[3][2][2];  // [ocpair][row r][col j]
    #pragma unroll
    for (int p = 0; p < 3; p++) {
        ull bv = pk(bias[2 * p], bias[2 * p + 1]);
        #pragma unroll
        for (int r = 0; r < 2; r++)
            #pragma unroll
            for (int j = 0; j < 2; j++) acc2[p][r][j] = bv;
    }

    #pragma unroll 1
    for (int c = 0; c < 3; c++) {
        #pragma unroll 1
        for (int kh = 0; kh < 5; kh++) {
            ull wreg[3][5];
            #pragma unroll
            for (int p = 0; p < 3; p++)
                #pragma unroll
                for (int kw = 0; kw < 5; kw++)
                    wreg[p][kw] = sW2[c][kh][kw][p];
            #pragma unroll
            for (int r = 0; r < 2; r++) {
                const int irow = 4 * ty + 2 * r + kh;
                #pragma unroll
                for (int j = 0; j < 2; j++) {
                    const int owl = tx + 32 * j;
                    // input col for (kw) = 2*owl + kw  -> E/O phase arrays
                    float e0 = sE[c][irow][owl];
                    float o0 = sO[c][irow][owl];
                    float e1 = sE[c][irow][owl + 1];
                    float o1 = sO[c][irow][owl + 1];
                    float e2 = sE[c][irow][owl + 2];
                    ull b2[5] = {pk(e0, e0), pk(o0, o0), pk(e1, e1),
                                 pk(o1, o1), pk(e2, e2)};
                    #pragma unroll
                    for (int p = 0; p < 3; p++)
                        #pragma unroll
                        for (int kw = 0; kw < 5; kw++)
                            ffma2(acc2[p][r][j], b2[kw], wreg[p][kw]);
                }
            }
        }
    }

    // relu -> smem
    #pragma unroll
    for (int p = 0; p < 3; p++)
        #pragma unroll
        for (int r = 0; r < 2; r++)
            #pragma unroll
            for (int j = 0; j < 2; j++) {
                float2 v = upk(acc2[p][r][j]);
                sOut[2 * p][2 * ty + r][tx + 32 * j]     = fmaxf(v.x, 0.f);
                sOut[2 * p + 1][2 * ty + r][tx + 32 * j] = fmaxf(v.y, 0.f);
            }
    __syncthreads();

    // fused 2x2 s1 maxpool -> g_pool1 [256,6,123,123]
    #pragma unroll
    for (int r = 0; r < 2; r++) {
        int prow = 2 * ty + r;
        if (prow >= 7) continue;
        int pr = oh0 + prow;
        if (pr >= 123) continue;
        #pragma unroll
        for (int j = 0; j < 2; j++) {
            int cl = tx + 32 * j;
            if (cl > 62) continue;
            int pc = ow0 + cl;
            if (pc >= 123) continue;
            #pragma unroll
            for (int oc = 0; oc < 6; oc++) {
                float m = fmaxf(fmaxf(sOut[oc][prow][cl], sOut[oc][prow][cl + 1]),
                                fmaxf(sOut[oc][prow + 1][cl], sOut[oc][prow + 1][cl + 1]));
                g_pool1[(((size_t)b * 6 + oc) * 123 + pr) * 123 + pc] = m;
            }
        }
    }
}

// ---------------- conv2 + relu + fused maxpool(2,2,s1) ----------------
// block (32,4): conv tile 62(ow full) x 8(oh); pool tile 61 x 7
// Even/odd phase-split input; f32x2 over oc-pairs (8 pairs, last padded).
__global__ __launch_bounds__(128) void conv2_kernel(
    const float* __restrict__ w, const float* __restrict__ bias)
{
    __shared__ float sE[17][64];
    __shared__ float sO[17][64];
    __shared__ ull   sW2[8][6][3][3];  // [ocpair][c][kh][kw], pair {2p,2p+1}, oc15->0
    __shared__ float sOut[15][8][63];
    const int b = blockIdx.z;
    const int oh0 = blockIdx.y * 7;
    const int tx = threadIdx.x, ty = threadIdx.y;
    const int tid = ty * 32 + tx;

    for (int i = tid; i < 432; i += 128) {
        int p = i / 54;
        int rem = i % 54;
        int c = rem / 9, kh = (rem / 3) % 3, kw = rem % 3;
        float w0 = w[((2 * p * 6 + c) * 3 + kh) * 3 + kw];
        float w1 = (2 * p + 1 < 15) ? w[(((2 * p + 1) * 6 + c) * 3 + kh) * 3 + kw] : 0.f;
        sW2[p][c][kh][kw] = pk(w0, w1);
    }

    ull acc2[8][2][2];
    #pragma unroll
    for (int p = 0; p < 8; p++) {
        ull bv = pk(bias[2 * p < 15 ? 2 * p : 0], (2 * p + 1 < 15) ? bias[2 * p + 1] : 0.f);
        if (2 * p >= 15) bv = 0ull;   // never happens (p<=7 -> 14), keep safe
        #pragma unroll
        for (int r = 0; r < 2; r++)
            #pragma unroll
            for (int j = 0; j < 2; j++) acc2[p][r][j] = bv;
    }

    const int ih0 = oh0 * 2 - 1;
    #pragma unroll 1
    for (int c = 0; c < 6; c++) {
        __syncthreads();
        const float* pin = g_pool1 + ((size_t)b * 6 + c) * 123 * 123;
        // input cols -1..123 -> tile cols 0..124 (125)
        for (int i = tid; i < 17 * 125; i += 128) {
            int r = i / 125, col = i % 125;
            int ih = ih0 + r, iw = col - 1;
            float v = 0.f;
            if (ih >= 0 && ih < 123 && iw >= 0 && iw < 123)
                v = pin[ih * 123 + iw];
            if (col & 1) sO[r][col >> 1] = v;
            else         sE[r][col >> 1] = v;
        }
        __syncthreads();
        #pragma unroll
        for (int kh = 0; kh < 3; kh++) {
            ull wreg[8][3];
            #pragma unroll
            for (int p = 0; p < 8; p++)
                #pragma unroll
                for (int kw = 0; kw < 3; kw++)
                    wreg[p][kw] = sW2[p][c][kh][kw];
            #pragma unroll
            for (int r = 0; r < 2; r++) {
                const int irow = 4 * ty + 2 * r + kh;
                #pragma unroll
                for (int j = 0; j < 2; j++) {
                    const int owl = tx + 32 * j;
                    if (owl > 61) continue;
                    float e0 = sE[irow][owl];
                    float o0 = sO[irow][owl];
                    float e1 = sE[irow][owl + 1];
                    ull b2[3] = {pk(e0, e0), pk(o0, o0), pk(e1, e1)};
                    #pragma unroll
                    for (int p = 0; p < 8; p++)
                        #pragma unroll
                        for (int kw = 0; kw < 3; kw++)
                            ffma2(acc2[p][r][j], b2[kw], wreg[p][kw]);
                }
            }
        }
    }

    // relu -> smem (conv cols 0..61)
    #pragma unroll
    for (int p = 0; p < 8; p++)
        #pragma unroll
        for (int r = 0; r < 2; r++)
            #pragma unroll
            for (int j = 0; j < 2; j++) {
                int cl = tx + 32 * j;
                if (cl > 61) continue;
                float2 v = upk(acc2[p][r][j]);
                sOut[2 * p][2 * ty + r][cl < 63 ? cl : 62] = fmaxf(v.x, 0.f);
                if (2 * p + 1 < 15)
                    sOut[2 * p + 1][2 * ty + r][cl < 63 ? cl : 62] = fmaxf(v.y, 0.f);
            }
    __syncthreads();

    // fused maxpool -> g_pool2 [256,15,61,61]
    #pragma unroll
    for (int r = 0; r < 2; r++) {
        int prow = 2 * ty + r;
        if (prow >= 7) continue;
        int pr = oh0 + prow;
        if (pr >= 61) continue;
        #pragma unroll
        for (int j = 0; j < 2; j++) {
            int cl = tx + 32 * j;
            if (cl > 60) continue;
            #pragma unroll
            for (int oc = 0; oc < 15; oc++) {
                float m = fmaxf(fmaxf(sOut[oc][prow][cl], sOut[oc][prow][cl + 1]),
                                fmaxf(sOut[oc][prow + 1][cl], sOut[oc][prow + 1][cl + 1]));
                g_pool2[(((size_t)b * 15 + oc) * 61 + pr) * 61 + cl] = m;
            }
        }
    }
}

// ---------------- fc1 split-K GEMM: [256,55815] x [120,55815]^T ----------------
// grid (4 M-tiles, 37 K-chunks) = 148 blocks; tile 64M x 120N; 256 threads
// f32x2 along K, LDS.64 operands, double-buffered smem + register prefetch
__global__ __launch_bounds__(256) void fc1_kernel(const float* __restrict__ W)
{
    __shared__ float sA[2][64][18];
    __shared__ float sW[2][128][18];
    const int m0 = blockIdx.x * 64;
    const int ks = blockIdx.y;
    const int kbeg = ks * KCHUNK;
    const int kend = (kbeg + KCHUNK < KDIM) ? kbeg + KCHUNK : KDIM;
    const int nIter = (kend - kbeg + 15) / 16;
    const int tid = threadIdx.x;
    const int tx = tid & 15, ty = tid >> 4;

    // fixed per-thread load slots
    int amr[4], akk[4], wnr[8], wkk[8];
    #pragma unroll
    for (int l = 0; l < 4; l++) { int i = tid + 256 * l; amr[l] = i >> 4; akk[l] = i & 15; }
    #pragma unroll
    for (int l = 0; l < 8; l++) { int i = tid + 256 * l; wnr[l] = i >> 4; wkk[l] = i & 15; }

    const float* A = g_pool2;
    float ra[4], rw[8];

    // prologue: load chunk 0
    #pragma unroll
    for (int l = 0; l < 4; l++) {
        int k = kbeg + akk[l];
        ra[l] = (k < kend) ? A[(size_t)(m0 + amr[l]) * KDIM + k] : 0.f;
    }
    #pragma unroll
    for (int l = 0; l < 8; l++) {
        int k = kbeg + wkk[l];
        rw[l] = (wnr[l] < 120 && k < kend) ? W[(size_t)wnr[l] * KDIM + k] : 0.f;
    }
    #pragma unroll
    for (int l = 0; l < 4; l++) sA[0][amr[l]][akk[l]] = ra[l];
    #pragma unroll
    for (int l = 0; l < 8; l++) sW[0][wnr[l]][wkk[l]] = rw[l];
    __syncthreads();

    ull acc2[4][8];
    #pragma unroll
    for (int i = 0; i < 4; i++)
        #pragma unroll
        for (int j = 0; j < 8; j++) acc2[i][j] = 0ull;

    int buf = 0;
    for (int it = 0; it < nIter; it++) {
        // prefetch next chunk into registers
        const int k0n = kbeg + (it + 1) * 16;
        const bool more = (it + 1 < nIter);
        if (more) {
            #pragma unroll
            for (int l = 0; l < 4; l++) {
                int k = k0n + akk[l];
                ra[l] = (k < kend) ? A[(size_t)(m0 + amr[l]) * KDIM + k] : 0.f;
            }
            #pragma unroll
            for (int l = 0; l < 8; l++) {
                int k = k0n + wkk[l];
                rw[l] = (wnr[l] < 120 && k < kend) ? W[(size_t)wnr[l] * KDIM + k] : 0.f;
            }
        }
        // compute on current buffer
        #pragma unroll
        for (int kk = 0; kk < 16; kk += 2) {
            ull a2[4], w2[8];
            #pragma unroll
            for (int i = 0; i < 4; i++)
                a2[i] = *reinterpret_cast<const ull*>(&sA[buf][ty * 4 + i][kk]);
            #pragma unroll
            for (int j = 0; j < 8; j++)
                w2[j] = *reinterpret_cast<const ull*>(&sW[buf][tx + 16 * j][kk]);
            #pragma unroll
            for (int i = 0; i < 4; i++)
                #pragma unroll
                for (int j = 0; j < 8; j++)
                    ffma2(acc2[i][j], a2[i], w2[j]);
        }
        // stage next buffer
        if (more) {
            #pragma unroll
            for (int l = 0; l < 4; l++) sA[buf ^ 1][amr[l]][akk[l]] = ra[l];
            #pragma unroll
            for (int l = 0; l < 8; l++) sW[buf ^ 1][wnr[l]][wkk[l]] = rw[l];
        }
        __syncthreads();
        buf ^= 1;
    }

    #pragma unroll
    for (int i = 0; i < 4; i++) {
        int m = m0 + ty * 4 + i;
        #pragma unroll
        for (int j = 0; j < 8; j++) {
            int n = tx + 16 * j;
            if (n < 120) {
                float2 v = upk(acc2[i][j]);
                g_part[((size_t)ks * BATCH + m) * 120 + n] = v.x + v.y;
            }
        }
    }
}

__global__ void fc1_reduce_kernel(const float* __restrict__ fc1_b)
{
    int idx = blockIdx.x * blockDim.x + threadIdx.x;
    if (idx >= BATCH * 120) return;
    int n = idx % 120;
    float s = fc1_b[n];
    #pragma unroll
    for (int ks = 0; ks < KSPLIT; ks++)
        s += g_part[(size_t)ks * BATCH * 120 + idx];
    g_h1[idx] = fmaxf(s, 0.f);
}

// ---------------- fc2 + fc3 + ParameterizedLayer + sigmoid ----------------
__global__ __launch_bounds__(128) void head_kernel(
    const float* __restrict__ fc2_w, const float* __restrict__ fc2_b,
    const float* __restrict__ fc3_w, const float* __restrict__ fc3_b,
    const float* __restrict__ pl_w, const float* __restrict__ pl_b,
    const float* __restrict__ pl_scale, const float* __restrict__ pl_bias)
{
    const int m = blockIdx.x;
    const int t = threadIdx.x;
    __shared__ float sh[120];
    __shared__ float sfeat[84];
    if (t < 120) sh[t] = g_h1[m * 120 + t];
    __syncthreads();
    if (t < 84) {
        float s = fc2_b[t];
        const float* wr = fc2_w + t * 120;
        #pragma unroll
        for (int k = 0; k < 120; k++) s = fmaf(sh[k], wr[k], s);
        g_feat[m * 84 + t] = s;
        sfeat[t] = s * fc3_w[t];
    }
    __syncthreads();
    if (t == 0) {
        float l = fc3_b[0];
        #pragma unroll
        for (int k = 0; k < 84; k++) l += sfeat[k];
        float z = tanhf(l * pl_w[0] + pl_b[0]) * pl_scale[0] + pl_bias[0];
        g_probs[m] = 1.f / (1.f + expf(-z));
    }
}

// ---------------- cosine-sign adjacency + degree-weighted aggregation ----------------
// sim >= 0  <=>  dot >= 0 (denominator strictly positive); exclude diagonal.
__global__ __launch_bounds__(256) void graph_kernel(float* __restrict__ out)
{
    const int i = blockIdx.x;
    const int j = threadIdx.x;
    __shared__ float sf[84];
    __shared__ float rc[8], rs[8];
    if (j < 84) sf[j] = g_feat[i * 84 + j];
    __syncthreads();

    const float* fj = g_feat + j * 84;
    float dot = 0.f;
    #pragma unroll
    for (int k = 0; k < 84; k++) dot = fmaf(sf[k], fj[k], dot);

    const bool adj = (dot >= 0.f) && (j != i);
    float c = adj ? 1.f : 0.f;
    float s = adj ? g_probs[j] : 0.f;
    #pragma unroll
    for (int o = 16; o > 0; o >>= 1) {
        c += __shfl_down_sync(0xffffffffu, c, o);
        s += __shfl_down_sync(0xffffffffu, s, o);
    }
    const int lane = j & 31, wrp = j >> 5;
    if (lane == 0) { rc[wrp] = c; rs[wrp] = s; }
    __syncthreads();
    if (j == 0) {
        float deg = 0.f, ss = 0.f;
        #pragma unroll
        for (int w2 = 0; w2 < 8; w2++) { deg += rc[w2]; ss += rs[w2]; }
        float neigh = (deg > 0.f) ? ss / fmaxf(deg, 1.f) : 0.f;
        float agg = (g_probs[i] + neigh) / (1.f + deg);
        out[2 * i]     = agg;
        out[2 * i + 1] = 1.f - agg;
    }
}

// ---------------- launch ----------------
extern "C" void kernel_launch(void* const* d_in, const int* in_sizes, int n_in,
                              void* d_out, int out_size)
{
    const float* x       = (const float*)d_in[0];
    const float* conv1_w = (const float*)d_in[1];
    const float* conv1_b = (const float*)d_in[2];
    const float* conv2_w = (const float*)d_in[3];
    const float* conv2_b = (const float*)d_in[4];
    const float* fc1_w   = (const float*)d_in[5];
    const float* fc1_b   = (const float*)d_in[6];
    const float* fc2_w   = (const float*)d_in[7];
    const float* fc2_b   = (const float*)d_in[8];
    const float* fc3_w   = (const float*)d_in[9];
    const float* fc3_b   = (const float*)d_in[10];
    const float* pl_w    = (const float*)d_in[11];
    const float* pl_b    = (const float*)d_in[12];
    const float* pl_scale= (const float*)d_in[13];
    const float* pl_bias = (const float*)d_in[14];
    float* out = (float*)d_out;

    conv1_kernel<<<dim3(2, 18, BATCH), dim3(32, 4)>>>(x, conv1_w, conv1_b);
    conv2_kernel<<<dim3(1, 9, BATCH), dim3(32, 4)>>>(conv2_w, conv2_b);
    fc1_kernel<<<dim3(4, KSPLIT), 256>>>(fc1_w);
    fc1_reduce_kernel<<<(BATCH * 120 + 255) / 256, 256>>>(fc1_b);
    head_kernel<<<BATCH, 128>>>(fc2_w, fc2_b, fc3_w, fc3_b, pl_w, pl_b, pl_scale, pl_bias);
    graph_kernel<<<BATCH, 256>>>(out);
}

// round 5
// speedup vs baseline: 1.4653x; 1.4653x over previous
#include <cuda_runtime.h>
#include <math.h>

// ---------------- problem constants ----------------
#define BATCH 256
// conv1: in [256,3,250,250], w [6,3,5,5], s2 p1 -> [256,6,124,124]
// pool1 (fused) -> [256,6,123,123]
// conv2: w [15,6,3,3], s2 p1 -> [256,15,62,62]
// pool2 (fused) -> [256,15,61,61]  (flatten K = 15*61*61 = 55815)
#define KDIM 55815
#define KSPLIT 37
#define KCHUNK 1536

// ---------------- scratch (static device arrays; no allocation) ----------------
__device__ float g_pool1[(size_t)BATCH * 6 * 123 * 123];   // 93.0 MB
__device__ float g_pool2[(size_t)BATCH * 15 * 61 * 61];    // 57.2 MB (fc1 "A")
__device__ float g_part[(size_t)KSPLIT * BATCH * 120];     // 4.5 MB
__device__ float g_h1[BATCH * 120];
__device__ float g_feat[BATCH * 84];
__device__ float g_probs[BATCH];

// ---------------- f32x2 helpers ----------------
typedef unsigned long long ull;
__device__ __forceinline__ ull pk(float lo, float hi) {
    ull r;
    asm("mov.b64 %0, {%1, %2};" : "=l"(r) : "f"(lo), "f"(hi));
    return r;
}
__device__ __forceinline__ void ffma2(ull& d, ull a, ull b) {
    asm("fma.rn.f32x2 %0, %1, %2, %0;" : "+l"(d) : "l"(a), "l"(b));
}
__device__ __forceinline__ float2 upk(ull v) {
    float2 r;
    asm("mov.b64 {%0, %1}, %2;" : "=f"(r.x), "=f"(r.y) : "l"(v));
    return r;
}

// ---------------- conv1 + relu + fused maxpool(2,2,s1) ----------------
// block (16,8): conv tile 64(ow) x 8(oh); pool tile 63 x 7 (grid.x step 60)
// f32x2 over oc-pairs; vectorized LDS.128 input loads.
__global__ __launch_bounds__(128) void conv1_kernel(
    const float* __restrict__ x, const float* __restrict__ w,
    const float* __restrict__ bias)
{
    __shared__ __align__(16) float sIn[3][19][132];
    __shared__ ull sW2[3][5][5][3];   // [c][kh][kw][ocpair]
    __shared__ float sOut[6][8][65];
    const int b = blockIdx.z;
    const int ow0 = blockIdx.x * 60;
    const int oh0 = blockIdx.y * 7;
    const int tx = threadIdx.x, ty = threadIdx.y;
    const int tid = ty * 16 + tx;

    // pack weights {w[2p], w[2p+1]} per (c,kh,kw)
    for (int i = tid; i < 225; i += 128) {
        int p = i % 3;
        int kw = (i / 3) % 5;
        int kh = (i / 15) % 5;
        int c = i / 75;
        float w0 = w[(((2 * p) * 3 + c) * 5 + kh) * 5 + kw];
        float w1 = w[(((2 * p + 1) * 3 + c) * 5 + kh) * 5 + kw];
        sW2[c][kh][kw][p] = pk(w0, w1);
    }

    const int ih0 = oh0 * 2 - 1;
    const int iw0 = ow0 * 2 - 1;
    const float* xb = x + (size_t)b * 3 * 250 * 250;
    for (int i = tid; i < 3 * 19 * 131; i += 128) {
        int c = i / (19 * 131);
        int rem = i % (19 * 131);
        int r = rem / 131, col = rem % 131;
        int ih = ih0 + r, iw = iw0 + col;
        float v = 0.f;
        if (ih >= 0 && ih < 250 && iw >= 0 && iw < 250)
            v = xb[(c * 250 + ih) * 250 + iw];
        sIn[c][r][col] = v;
    }
    __syncthreads();

    ull acc2[3][4];
    #pragma unroll
    for (int p = 0; p < 3; p++) {
        ull bv = pk(bias[2 * p], bias[2 * p + 1]);
        #pragma unroll
        for (int j = 0; j < 4; j++) acc2[p][j] = bv;
    }

    #pragma unroll 1
    for (int c = 0; c < 3; c++) {
        #pragma unroll 1
        for (int kh = 0; kh < 5; kh++) {
            // vector loads: cols tx*8 .. tx*8+11 (row stride 528B, 16B-aligned)
            const float4* rowv =
                reinterpret_cast<const float4*>(&sIn[c][ty * 2 + kh][tx * 8]);
            float4 f0 = rowv[0];
            float4 f1 = rowv[1];
            float4 f2 = rowv[2];
            float in[11] = {f0.x, f0.y, f0.z, f0.w,
                            f1.x, f1.y, f1.z, f1.w,
                            f2.x, f2.y, f2.z};
            ull b2[11];
            #pragma unroll
            for (int i = 0; i < 11; i++) b2[i] = pk(in[i], in[i]);
            #pragma unroll
            for (int p = 0; p < 3; p++) {
                #pragma unroll
                for (int kw = 0; kw < 5; kw++) {
                    ull wv = sW2[c][kh][kw][p];
                    #pragma unroll
                    for (int j = 0; j < 4; j++)
                        ffma2(acc2[p][j], b2[2 * j + kw], wv);
                }
            }
        }
    }

    // relu -> smem
    #pragma unroll
    for (int p = 0; p < 3; p++) {
        #pragma unroll
        for (int j = 0; j < 4; j++) {
            float2 v = upk(acc2[p][j]);
            sOut[2 * p][ty][tx * 4 + j] = fmaxf(v.x, 0.f);
            sOut[2 * p + 1][ty][tx * 4 + j] = fmaxf(v.y, 0.f);
        }
    }
    __syncthreads();

    // fused 2x2 s1 maxpool -> g_pool1 [256,6,123,123]
    if (ty < 7) {
        int pr = oh0 + ty;
        if (pr < 123) {
            #pragma unroll
            for (int oc = 0; oc < 6; oc++) {
                #pragma unroll
                for (int j = 0; j < 4; j++) {
                    int cl = tx * 4 + j;
                    if (cl > 62) continue;
                    int pc = ow0 + cl;
                    if (pc >= 123) continue;
                    float m = fmaxf(fmaxf(sOut[oc][ty][cl], sOut[oc][ty][cl + 1]),
                                    fmaxf(sOut[oc][ty + 1][cl], sOut[oc][ty + 1][cl + 1]));
                    g_pool1[(((size_t)b * 6 + oc) * 123 + pr) * 123 + pc] = m;
                }
            }
        }
    }
}

// ---------------- conv2 + relu + fused maxpool(2,2,s1) ----------------
// block (16,8): conv tile 62(ow full) x 8(oh); pool tile 61 x 7
// f32x2 over ow-pairs; vectorized LDS.128 input loads.
__global__ __launch_bounds__(128) void conv2_kernel(
    const float* __restrict__ w, const float* __restrict__ bias)
{
    __shared__ __align__(16) float sIn[17][132];
    __shared__ ull sW2[15][6][3][3];  // duplicated {w,w}
    __shared__ float sOut[15][8][63];
    const int b = blockIdx.z;
    const int oh0 = blockIdx.y * 7;
    const int tx = threadIdx.x, ty = threadIdx.y;
    const int tid = ty * 16 + tx;

    for (int i = tid; i < 810; i += 128) {
        float wv = w[i];
        int kw = i % 3, kh = (i / 3) % 3, c = (i / 9) % 6, oc = i / 54;
        sW2[oc][c][kh][kw] = pk(wv, wv);
    }

    ull acc2[15][2];
    #pragma unroll
    for (int oc = 0; oc < 15; oc++) {
        acc2[oc][0] = 0ull; acc2[oc][1] = 0ull;
    }

    const int ih0 = oh0 * 2 - 1;
    #pragma unroll 1
    for (int c = 0; c < 6; c++) {
        __syncthreads();
        const float* pin = g_pool1 + ((size_t)b * 6 + c) * 123 * 123;
        for (int i = tid; i < 17 * 129; i += 128) {
            int r = i / 129, col = i % 129;
            int ih = ih0 + r, iw = col - 1;
            float v = 0.f;
            if (ih >= 0 && ih < 123 && iw >= 0 && iw < 123)
                v = pin[ih * 123 + iw];
            sIn[r][col] = v;
        }
        __syncthreads();
        #pragma unroll 1
        for (int kh = 0; kh < 3; kh++) {
            const float* row = &sIn[ty * 2 + kh][tx * 8];
            const float4* rowv = reinterpret_cast<const float4*>(row);
            float4 f0 = rowv[0];
            float4 f1 = rowv[1];
            float in8 = row[8];
            float in[9] = {f0.x, f0.y, f0.z, f0.w, f1.x, f1.y, f1.z, f1.w, in8};
            ull p01[3], p23[3];
            #pragma unroll
            for (int kw = 0; kw < 3; kw++) {
                p01[kw] = pk(in[kw], in[kw + 2]);
                p23[kw] = pk(in[kw + 4], in[kw + 6]);
            }
            #pragma unroll
            for (int oc = 0; oc < 15; oc++) {
                #pragma unroll
                for (int kw = 0; kw < 3; kw++) {
                    ull wv = sW2[oc][c][kh][kw];
                    ffma2(acc2[oc][0], p01[kw], wv);
                    ffma2(acc2[oc][1], p23[kw], wv);
                }
            }
        }
    }

    // bias + relu -> smem (conv cols 0..61)
    #pragma unroll
    for (int oc = 0; oc < 15; oc++) {
        float bv = bias[oc];
        float2 v0 = upk(acc2[oc][0]);
        float2 v1 = upk(acc2[oc][1]);
        float vals[4] = {v0.x, v0.y, v1.x, v1.y};
        #pragma unroll
        for (int j = 0; j < 4; j++) {
            int cl = tx * 4 + j;
            if (cl < 62) sOut[oc][ty][cl] = fmaxf(vals[j] + bv, 0.f);
        }
    }
    __syncthreads();

    // fused maxpool -> g_pool2 [256,15,61,61]
    if (ty < 7) {
        int pr = oh0 + ty;
        if (pr < 61) {
            #pragma unroll
            for (int oc = 0; oc < 15; oc++) {
                #pragma unroll
                for (int j = 0; j < 4; j++) {
                    int cl = tx * 4 + j;
                    if (cl > 60) continue;
                    float m = fmaxf(fmaxf(sOut[oc][ty][cl], sOut[oc][ty][cl + 1]),
                                    fmaxf(sOut[oc][ty + 1][cl], sOut[oc][ty + 1][cl + 1]));
                    g_pool2[(((size_t)b * 15 + oc) * 61 + pr) * 61 + cl] = m;
                }
            }
        }
    }
}

// ---------------- fc1 split-K GEMM: [256,55815] x [120,55815]^T ----------------
// grid (4 M-tiles, 37 K-chunks) = 148 blocks; tile 64M x 120N; 256 threads
// f32x2 along K (even/odd lanes), LDS.64 operands  (R2-proven version)
__global__ __launch_bounds__(256) void fc1_kernel(const float* __restrict__ W)
{
    __shared__ float sA[64][18];
    __shared__ float sW[128][18];
    const int m0 = blockIdx.x * 64;
    const int ks = blockIdx.y;
    const int kbeg = ks * KCHUNK;
    const int kend = (kbeg + KCHUNK < KDIM) ? kbeg + KCHUNK : KDIM;
    const int tid = threadIdx.x;
    const int tx = tid & 15, ty = tid >> 4;

    ull acc2[4][8];
    #pragma unroll
    for (int i = 0; i < 4; i++)
        #pragma unroll
        for (int j = 0; j < 8; j++) acc2[i][j] = 0ull;

    const float* A = g_pool2;

    for (int k0 = kbeg; k0 < kend; k0 += 16) {
        #pragma unroll
        for (int i = tid; i < 64 * 16; i += 256) {
            int m = i >> 4, kk = i & 15;
            int k = k0 + kk;
            sA[m][kk] = (k < kend) ? A[(size_t)(m0 + m) * KDIM + k] : 0.f;
        }
        #pragma unroll
        for (int i = tid; i < 128 * 16; i += 256) {
            int n = i >> 4, kk = i & 15;
            int k = k0 + kk;
            sW[n][kk] = (n < 120 && k < kend) ? W[(size_t)n * KDIM + k] : 0.f;
        }
        __syncthreads();
        #pragma unroll
        for (int kk = 0; kk < 16; kk += 2) {
            ull a2[4], w2[8];
            #pragma unroll
            for (int i = 0; i < 4; i++)
                a2[i] = *reinterpret_cast<const ull*>(&sA[ty * 4 + i][kk]);
            #pragma unroll
            for (int j = 0; j < 8; j++)
                w2[j] = *reinterpret_cast<const ull*>(&sW[tx + 16 * j][kk]);
            #pragma unroll
            for (int i = 0; i < 4; i++)
                #pragma unroll
                for (int j = 0; j < 8; j++)
                    ffma2(acc2[i][j], a2[i], w2[j]);
        }
        __syncthreads();
    }

    #pragma unroll
    for (int i = 0; i < 4; i++) {
        int m = m0 + ty * 4 + i;
        #pragma unroll
        for (int j = 0; j < 8; j++) {
            int n = tx + 16 * j;
            if (n < 120) {
                float2 v = upk(acc2[i][j]);
                g_part[((size_t)ks * BATCH + m) * 120 + n] = v.x + v.y;
            }
        }
    }
}

__global__ void fc1_reduce_kernel(const float* __restrict__ fc1_b)
{
    int idx = blockIdx.x * blockDim.x + threadIdx.x;
    if (idx >= BATCH * 120) return;
    int n = idx % 120;
    float s = fc1_b[n];
    #pragma unroll
    for (int ks = 0; ks < KSPLIT; ks++)
        s += g_part[(size_t)ks * BATCH * 120 + idx];
    g_h1[idx] = fmaxf(s, 0.f);
}

// ---------------- fc2 + fc3 + ParameterizedLayer + sigmoid ----------------
__global__ __launch_bounds__(128) void head_kernel(
    const float* __restrict__ fc2_w, const float* __restrict__ fc2_b,
    const float* __restrict__ fc3_w, const float* __restrict__ fc3_b,
    const float* __restrict__ pl_w, const float* __restrict__ pl_b,
    const float* __restrict__ pl_scale, const float* __restrict__ pl_bias)
{
    const int m = blockIdx.x;
    const int t = threadIdx.x;
    __shared__ float sh[120];
    __shared__ float sfeat[84];
    if (t < 120) sh[t] = g_h1[m * 120 + t];
    __syncthreads();
    if (t < 84) {
        float s = fc2_b[t];
        const float* wr = fc2_w + t * 120;
        #pragma unroll
        for (int k = 0; k < 120; k++) s = fmaf(sh[k], wr[k], s);
        g_feat[m * 84 + t] = s;
        sfeat[t] = s * fc3_w[t];
    }
    __syncthreads();
    if (t == 0) {
        float l = fc3_b[0];
        #pragma unroll
        for (int k = 0; k < 84; k++) l += sfeat[k];
        float z = tanhf(l * pl_w[0] + pl_b[0]) * pl_scale[0] + pl_bias[0];
        g_probs[m] = 1.f / (1.f + expf(-z));
    }
}

// ---------------- cosine-sign adjacency + degree-weighted aggregation ----------------
// sim >= 0  <=>  dot >= 0 (denominator strictly positive); exclude diagonal.
__global__ __launch_bounds__(256) void graph_kernel(float* __restrict__ out)
{
    const int i = blockIdx.x;
    const int j = threadIdx.x;
    __shared__ float sf[84];
    __shared__ float rc[8], rs[8];
    if (j < 84) sf[j] = g_feat[i * 84 + j];
    __syncthreads();

    const float* fj = g_feat + j * 84;
    float dot = 0.f;
    #pragma unroll
    for (int k = 0; k < 84; k++) dot = fmaf(sf[k], fj[k], dot);

    const bool adj = (dot >= 0.f) && (j != i);
    float c = adj ? 1.f : 0.f;
    float s = adj ? g_probs[j] : 0.f;
    #pragma unroll
    for (int o = 16; o > 0; o >>= 1) {
        c += __shfl_down_sync(0xffffffffu, c, o);
        s += __shfl_down_sync(0xffffffffu, s, o);
    }
    const int lane = j & 31, wrp = j >> 5;
    if (lane == 0) { rc[wrp] = c; rs[wrp] = s; }
    __syncthreads();
    if (j == 0) {
        float deg = 0.f, ss = 0.f;
        #pragma unroll
        for (int w2 = 0; w2 < 8; w2++) { deg += rc[w2]; ss += rs[w2]; }
        float neigh = (deg > 0.f) ? ss / fmaxf(deg, 1.f) : 0.f;
        float agg = (g_probs[i] + neigh) / (1.f + deg);
        out[2 * i]     = agg;
        out[2 * i + 1] = 1.f - agg;
    }
}

// ---------------- launch ----------------
extern "C" void kernel_launch(void* const* d_in, const int* in_sizes, int n_in,
                              void* d_out, int out_size)
{
    const float* x       = (const float*)d_in[0];
    const float* conv1_w = (const float*)d_in[1];
    const float* conv1_b = (const float*)d_in[2];
    const float* conv2_w = (const float*)d_in[3];
    const float* conv2_b = (const float*)d_in[4];
    const float* fc1_w   = (const float*)d_in[5];
    const float* fc1_b   = (const float*)d_in[6];
    const float* fc2_w   = (const float*)d_in[7];
    const float* fc2_b   = (const float*)d_in[8];
    const float* fc3_w   = (const float*)d_in[9];
    const float* fc3_b   = (const float*)d_in[10];
    const float* pl_w    = (const float*)d_in[11];
    const float* pl_b    = (const float*)d_in[12];
    const float* pl_scale= (const float*)d_in[13];
    const float* pl_bias = (const float*)d_in[14];
    float* out = (float*)d_out;

    conv1_kernel<<<dim3(2, 18, BATCH), dim3(16, 8)>>>(x, conv1_w, conv1_b);
    conv2_kernel<<<dim3(1, 9, BATCH), dim3(16, 8)>>>(conv2_w, conv2_b);
    fc1_kernel<<<dim3(4, KSPLIT), 256>>>(fc1_w);
    fc1_reduce_kernel<<<(BATCH * 120 + 255) / 256, 256>>>(fc1_b);
    head_kernel<<<BATCH, 128>>>(fc2_w, fc2_b, fc3_w, fc3_b, pl_w, pl_b, pl_scale, pl_bias);
    graph_kernel<<<BATCH, 256>>>(out);
}

// round 6
// speedup vs baseline: 1.7827x; 1.2166x over previous
#include <cuda_runtime.h>
#include <math.h>

// ---------------- problem constants ----------------
#define BATCH 256
// conv1: in [256,3,250,250], w [6,3,5,5], s2 p1 -> [256,6,124,124]
// pool1 (fused) -> [256,6,123,123]
// conv2: w [15,6,3,3], s2 p1 -> [256,15,62,62]
// pool2 (fused) -> [256,15,61,61]  (flatten K = 15*61*61 = 55815)
#define KDIM 55815
#define KSPLIT 37
#define KCHUNK 1536

// ---------------- scratch (static device arrays; no allocation) ----------------
__device__ float g_pool1[(size_t)BATCH * 6 * 123 * 123];   // 93.0 MB
__device__ float g_pool2[(size_t)BATCH * 15 * 61 * 61];    // 57.2 MB (fc1 "A")
__device__ float g_part[(size_t)KSPLIT * BATCH * 120];     // 4.5 MB
__device__ float g_feat[BATCH * 84];
__device__ float g_probs[BATCH];

// ---------------- f32x2 helpers ----------------
typedef unsigned long long ull;
__device__ __forceinline__ ull pk(float lo, float hi) {
    ull r;
    asm("mov.b64 %0, {%1, %2};" : "=l"(r) : "f"(lo), "f"(hi));
    return r;
}
__device__ __forceinline__ void ffma2(ull& d, ull a, ull b) {
    asm("fma.rn.f32x2 %0, %1, %2, %0;" : "+l"(d) : "l"(a), "l"(b));
}
__device__ __forceinline__ float2 upk(ull v) {
    float2 r;
    asm("mov.b64 {%0, %1}, %2;" : "=f"(r.x), "=f"(r.y) : "l"(v));
    return r;
}

// ---------------- conv1 + relu + fused maxpool(2,2,s1) ----------------
// block (16,8): conv tile 64(ow) x 8(oh); pool tile 63 x 7 (grid.x step 60)
// f32x2 over oc-pairs; LDS.128 input loads; sOut ALIASED onto sIn (occupancy).
__global__ __launch_bounds__(128, 6) void conv1_kernel(
    const float* __restrict__ x, const float* __restrict__ w,
    const float* __restrict__ bias)
{
    __shared__ __align__(16) float sIn[3][19][132];   // 30.1 KB
    __shared__ ull sW2[3][5][5][3];                   // [c][kh][kw][ocpair]
    // pool staging buffer aliases sIn (dead after compute; barrier-ordered)
    float (*sOut)[8][65] = reinterpret_cast<float (*)[8][65]>(&sIn[0][0][0]);
    const int b = blockIdx.z;
    const int ow0 = blockIdx.x * 60;
    const int oh0 = blockIdx.y * 7;
    const int tx = threadIdx.x, ty = threadIdx.y;
    const int tid = ty * 16 + tx;

    // pack weights {w[2p], w[2p+1]} per (c,kh,kw)
    for (int i = tid; i < 225; i += 128) {
        int p = i % 3;
        int kw = (i / 3) % 5;
        int kh = (i / 15) % 5;
        int c = i / 75;
        float w0 = w[(((2 * p) * 3 + c) * 5 + kh) * 5 + kw];
        float w1 = w[(((2 * p + 1) * 3 + c) * 5 + kh) * 5 + kw];
        sW2[c][kh][kw][p] = pk(w0, w1);
    }

    const int ih0 = oh0 * 2 - 1;
    const int iw0 = ow0 * 2 - 1;
    const float* xb = x + (size_t)b * 3 * 250 * 250;
    for (int i = tid; i < 3 * 19 * 131; i += 128) {
        int c = i / (19 * 131);
        int rem = i % (19 * 131);
        int r = rem / 131, col = rem % 131;
        int ih = ih0 + r, iw = iw0 + col;
        float v = 0.f;
        if (ih >= 0 && ih < 250 && iw >= 0 && iw < 250)
            v = xb[(c * 250 + ih) * 250 + iw];
        sIn[c][r][col] = v;
    }
    __syncthreads();

    ull acc2[3][4];
    #pragma unroll
    for (int p = 0; p < 3; p++) {
        ull bv = pk(bias[2 * p], bias[2 * p + 1]);
        #pragma unroll
        for (int j = 0; j < 4; j++) acc2[p][j] = bv;
    }

    #pragma unroll 1
    for (int c = 0; c < 3; c++) {
        #pragma unroll 1
        for (int kh = 0; kh < 5; kh++) {
            // vector loads: cols tx*8 .. tx*8+11 (row stride 528B, 16B-aligned)
            const float4* rowv =
                reinterpret_cast<const float4*>(&sIn[c][ty * 2 + kh][tx * 8]);
            float4 f0 = rowv[0];
            float4 f1 = rowv[1];
            float4 f2 = rowv[2];
            float in[11] = {f0.x, f0.y, f0.z, f0.w,
                            f1.x, f1.y, f1.z, f1.w,
                            f2.x, f2.y, f2.z};
            ull b2[11];
            #pragma unroll
            for (int i = 0; i < 11; i++) b2[i] = pk(in[i], in[i]);
            #pragma unroll
            for (int p = 0; p < 3; p++) {
                #pragma unroll
                for (int kw = 0; kw < 5; kw++) {
                    ull wv = sW2[c][kh][kw][p];
                    #pragma unroll
                    for (int j = 0; j < 4; j++)
                        ffma2(acc2[p][j], b2[2 * j + kw], wv);
                }
            }
        }
    }

    // barrier: everyone done READING sIn before we overwrite it via alias
    __syncthreads();

    // relu -> smem (aliased)
    #pragma unroll
    for (int p = 0; p < 3; p++) {
        #pragma unroll
        for (int j = 0; j < 4; j++) {
            float2 v = upk(acc2[p][j]);
            sOut[2 * p][ty][tx * 4 + j] = fmaxf(v.x, 0.f);
            sOut[2 * p + 1][ty][tx * 4 + j] = fmaxf(v.y, 0.f);
        }
    }
    __syncthreads();

    // fused 2x2 s1 maxpool -> g_pool1 [256,6,123,123]
    if (ty < 7) {
        int pr = oh0 + ty;
        if (pr < 123) {
            #pragma unroll
            for (int oc = 0; oc < 6; oc++) {
                #pragma unroll
                for (int j = 0; j < 4; j++) {
                    int cl = tx * 4 + j;
                    if (cl > 62) continue;
                    int pc = ow0 + cl;
                    if (pc >= 123) continue;
                    float m = fmaxf(fmaxf(sOut[oc][ty][cl], sOut[oc][ty][cl + 1]),
                                    fmaxf(sOut[oc][ty + 1][cl], sOut[oc][ty + 1][cl + 1]));
                    g_pool1[(((size_t)b * 6 + oc) * 123 + pr) * 123 + pc] = m;
                }
            }
        }
    }
}

// ---------------- conv2 + relu + fused maxpool(2,2,s1) ----------------
// block (16,8): conv tile 62(ow full) x 8(oh); pool tile 61 x 7
// f32x2 over ow-pairs; LDS.128 input loads; register-prefetch next channel.
__global__ __launch_bounds__(128) void conv2_kernel(
    const float* __restrict__ w, const float* __restrict__ bias)
{
    __shared__ __align__(16) float sIn[17][132];
    __shared__ ull sW2[15][6][3][3];  // duplicated {w,w}
    __shared__ float sOut[15][8][63];
    const int b = blockIdx.z;
    const int oh0 = blockIdx.y * 7;
    const int tx = threadIdx.x, ty = threadIdx.y;
    const int tid = ty * 16 + tx;

    for (int i = tid; i < 810; i += 128) {
        float wv = w[i];
        int kw = i % 3, kh = (i / 3) % 3, c = (i / 9) % 6, oc = i / 54;
        sW2[oc][c][kh][kw] = pk(wv, wv);
    }

    ull acc2[15][2];
    #pragma unroll
    for (int oc = 0; oc < 15; oc++) {
        acc2[oc][0] = 0ull; acc2[oc][1] = 0ull;
    }

    const int ih0 = oh0 * 2 - 1;
    const float* pb = g_pool1 + (size_t)b * 6 * 123 * 123;

    // load channel 0 tile (cols -1..123 -> tile cols 0..124)
    for (int i = tid; i < 17 * 125; i += 128) {
        int r = i / 125, col = i % 125;
        int ih = ih0 + r, iw = col - 1;
        float v = 0.f;
        if (ih >= 0 && ih < 123 && iw >= 0 && iw < 123)
            v = pb[ih * 123 + iw];
        sIn[r][col] = v;
    }
    __syncthreads();

    #pragma unroll 1
    for (int c = 0; c < 6; c++) {
        // prefetch next channel's tile into registers (LDG overlapped w/ compute)
        float rN[17];
        if (c < 5) {
            const float* pin = pb + (size_t)(c + 1) * 123 * 123;
            #pragma unroll
            for (int l = 0; l < 17; l++) {
                int i = tid + 128 * l;
                float v = 0.f;
                if (i < 17 * 125) {
                    int r = i / 125, col = i % 125;
                    int ih = ih0 + r, iw = col - 1;
                    if (ih >= 0 && ih < 123 && iw >= 0 && iw < 123)
                        v = pin[ih * 123 + iw];
                }
                rN[l] = v;
            }
        }

        #pragma unroll 1
        for (int kh = 0; kh < 3; kh++) {
            const float* row = &sIn[ty * 2 + kh][tx * 8];
            const float4* rowv = reinterpret_cast<const float4*>(row);
            float4 f0 = rowv[0];
            float4 f1 = rowv[1];
            float in8 = row[8];
            float in[9] = {f0.x, f0.y, f0.z, f0.w, f1.x, f1.y, f1.z, f1.w, in8};
            ull p01[3], p23[3];
            #pragma unroll
            for (int kw = 0; kw < 3; kw++) {
                p01[kw] = pk(in[kw], in[kw + 2]);
                p23[kw] = pk(in[kw + 4], in[kw + 6]);
            }
            #pragma unroll
            for (int oc = 0; oc < 15; oc++) {
                #pragma unroll
                for (int kw = 0; kw < 3; kw++) {
                    ull wv = sW2[oc][c][kh][kw];
                    ffma2(acc2[oc][0], p01[kw], wv);
                    ffma2(acc2[oc][1], p23[kw], wv);
                }
            }
        }
        __syncthreads();     // done reading sIn
        if (c < 5) {
            #pragma unroll
            for (int l = 0; l < 17; l++) {
                int i = tid + 128 * l;
                if (i < 17 * 125) {
                    int r = i / 125, col = i % 125;
                    sIn[r][col] = rN[l];
                }
            }
            __syncthreads(); // sIn ready for next channel
        }
    }

    // bias + relu -> smem (conv cols 0..61)
    #pragma unroll
    for (int oc = 0; oc < 15; oc++) {
        float bv = bias[oc];
        float2 v0 = upk(acc2[oc][0]);
        float2 v1 = upk(acc2[oc][1]);
        float vals[4] = {v0.x, v0.y, v1.x, v1.y};
        #pragma unroll
        for (int j = 0; j < 4; j++) {
            int cl = tx * 4 + j;
            if (cl < 62) sOut[oc][ty][cl] = fmaxf(vals[j] + bv, 0.f);
        }
    }
    __syncthreads();

    // fused maxpool -> g_pool2 [256,15,61,61]
    if (ty < 7) {
        int pr = oh0 + ty;
        if (pr < 61) {
            #pragma unroll
            for (int oc = 0; oc < 15; oc++) {
                #pragma unroll
                for (int j = 0; j < 4; j++) {
                    int cl = tx * 4 + j;
                    if (cl > 60) continue;
                    float m = fmaxf(fmaxf(sOut[oc][ty][cl], sOut[oc][ty][cl + 1]),
                                    fmaxf(sOut[oc][ty + 1][cl], sOut[oc][ty + 1][cl + 1]));
                    g_pool2[(((size_t)b * 15 + oc) * 61 + pr) * 61 + cl] = m;
                }
            }
        }
    }
}

// ---------------- fc1 split-K GEMM: [256,55815] x [120,55815]^T ----------------
// grid (4 M-tiles, 37 K-chunks) = 148 blocks; tile 64M x 120N; 256 threads
// f32x2 along K, LDS.64 operands, double-buffered smem + register prefetch
__global__ __launch_bounds__(256) void fc1_kernel(const float* __restrict__ W)
{
    __shared__ float sA[2][64][18];
    __shared__ float sW[2][128][18];
    const int m0 = blockIdx.x * 64;
    const int ks = blockIdx.y;
    const int kbeg = ks * KCHUNK;
    const int kend = (kbeg + KCHUNK < KDIM) ? kbeg + KCHUNK : KDIM;
    const int nIter = (kend - kbeg + 15) / 16;
    const int tid = threadIdx.x;
    const int tx = tid & 15, ty = tid >> 4;

    // fixed per-thread load slots
    int amr[4], akk[4], wnr[8], wkk[8];
    #pragma unroll
    for (int l = 0; l < 4; l++) { int i = tid + 256 * l; amr[l] = i >> 4; akk[l] = i & 15; }
    #pragma unroll
    for (int l = 0; l < 8; l++) { int i = tid + 256 * l; wnr[l] = i >> 4; wkk[l] = i & 15; }

    const float* A = g_pool2;
    float ra[4], rw[8];

    // prologue: load chunk 0
    #pragma unroll
    for (int l = 0; l < 4; l++) {
        int k = kbeg + akk[l];
        ra[l] = (k < kend) ? A[(size_t)(m0 + amr[l]) * KDIM + k] : 0.f;
    }
    #pragma unroll
    for (int l = 0; l < 8; l++) {
        int k = kbeg + wkk[l];
        rw[l] = (wnr[l] < 120 && k < kend) ? W[(size_t)wnr[l] * KDIM + k] : 0.f;
    }
    #pragma unroll
    for (int l = 0; l < 4; l++) sA[0][amr[l]][akk[l]] = ra[l];
    #pragma unroll
    for (int l = 0; l < 8; l++) sW[0][wnr[l]][wkk[l]] = rw[l];
    __syncthreads();

    ull acc2[4][8];
    #pragma unroll
    for (int i = 0; i < 4; i++)
        #pragma unroll
        for (int j = 0; j < 8; j++) acc2[i][j] = 0ull;

    int buf = 0;
    for (int it = 0; it < nIter; it++) {
        const int k0n = kbeg + (it + 1) * 16;
        const bool more = (it + 1 < nIter);
        if (more) {
            #pragma unroll
            for (int l = 0; l < 4; l++) {
                int k = k0n + akk[l];
                ra[l] = (k < kend) ? A[(size_t)(m0 + amr[l]) * KDIM + k] : 0.f;
            }
            #pragma unroll
            for (int l = 0; l < 8; l++) {
                int k = k0n + wkk[l];
                rw[l] = (wnr[l] < 120 && k < kend) ? W[(size_t)wnr[l] * KDIM + k] : 0.f;
            }
        }
        #pragma unroll
        for (int kk = 0; kk < 16; kk += 2) {
            ull a2[4], w2[8];
            #pragma unroll
            for (int i = 0; i < 4; i++)
                a2[i] = *reinterpret_cast<const ull*>(&sA[buf][ty * 4 + i][kk]);
            #pragma unroll
            for (int j = 0; j < 8; j++)
                w2[j] = *reinterpret_cast<const ull*>(&sW[buf][tx + 16 * j][kk]);
            #pragma unroll
            for (int i = 0; i < 4; i++)
                #pragma unroll
                for (int j = 0; j < 8; j++)
                    ffma2(acc2[i][j], a2[i], w2[j]);
        }
        if (more) {
            #pragma unroll
            for (int l = 0; l < 4; l++) sA[buf ^ 1][amr[l]][akk[l]] = ra[l];
            #pragma unroll
            for (int l = 0; l < 8; l++) sW[buf ^ 1][wnr[l]][wkk[l]] = rw[l];
        }
        __syncthreads();
        buf ^= 1;
    }

    #pragma unroll
    for (int i = 0; i < 4; i++) {
        int m = m0 + ty * 4 + i;
        #pragma unroll
        for (int j = 0; j < 8; j++) {
            int n = tx + 16 * j;
            if (n < 120) {
                float2 v = upk(acc2[i][j]);
                g_part[((size_t)ks * BATCH + m) * 120 + n] = v.x + v.y;
            }
        }
    }
}

// ---------------- fused: split-K reduce + fc2 + fc3 + PL + sigmoid ----------------
__global__ __launch_bounds__(128) void head_kernel(
    const float* __restrict__ fc1_b,
    const float* __restrict__ fc2_w, const float* __restrict__ fc2_b,
    const float* __restrict__ fc3_w, const float* __restrict__ fc3_b,
    const float* __restrict__ pl_w, const float* __restrict__ pl_b,
    const float* __restrict__ pl_scale, const float* __restrict__ pl_bias)
{
    const int m = blockIdx.x;
    const int t = threadIdx.x;
    __shared__ float sh[120];
    __shared__ float sfeat[84];
    if (t < 120) {
        float s = fc1_b[t];
        const float* p = g_part + (size_t)m * 120 + t;
        #pragma unroll
        for (int ks = 0; ks < KSPLIT; ks++)
            s += p[(size_t)ks * BATCH * 120];
        sh[t] = fmaxf(s, 0.f);
    }
    __syncthreads();
    if (t < 84) {
        float s = fc2_b[t];
        const float* wr = fc2_w + t * 120;
        #pragma unroll
        for (int k = 0; k < 120; k++) s = fmaf(sh[k], wr[k], s);
        g_feat[m * 84 + t] = s;
        sfeat[t] = s * fc3_w[t];
    }
    __syncthreads();
    if (t == 0) {
        float l = fc3_b[0];
        #pragma unroll
        for (int k = 0; k < 84; k++) l += sfeat[k];
        float z = tanhf(l * pl_w[0] + pl_b[0]) * pl_scale[0] + pl_bias[0];
        g_probs[m] = 1.f / (1.f + expf(-z));
    }
}

// ---------------- cosine-sign adjacency + degree-weighted aggregation ----------------
// sim >= 0  <=>  dot >= 0 (denominator strictly positive); exclude diagonal.
__global__ __launch_bounds__(256) void graph_kernel(float* __restrict__ out)
{
    const int i = blockIdx.x;
    const int j = threadIdx.x;
    __shared__ float sf[84];
    __shared__ float rc[8], rs[8];
    if (j < 84) sf[j] = g_feat[i * 84 + j];
    __syncthreads();

    const float* fj = g_feat + j * 84;
    float dot = 0.f;
    #pragma unroll
    for (int k = 0; k < 84; k++) dot = fmaf(sf[k], fj[k], dot);

    const bool adj = (dot >= 0.f) && (j != i);
    float c = adj ? 1.f : 0.f;
    float s = adj ? g_probs[j] : 0.f;
    #pragma unroll
    for (int o = 16; o > 0; o >>= 1) {
        c += __shfl_down_sync(0xffffffffu, c, o);
        s += __shfl_down_sync(0xffffffffu, s, o);
    }
    const int lane = j & 31, wrp = j >> 5;
    if (lane == 0) { rc[wrp] = c; rs[wrp] = s; }
    __syncthreads();
    if (j == 0) {
        float deg = 0.f, ss = 0.f;
        #pragma unroll
        for (int w2 = 0; w2 < 8; w2++) { deg += rc[w2]; ss += rs[w2]; }
        float neigh = (deg > 0.f) ? ss / fmaxf(deg, 1.f) : 0.f;
        float agg = (g_probs[i] + neigh) / (1.f + deg);
        out[2 * i]     = agg;
        out[2 * i + 1] = 1.f - agg;
    }
}

// ---------------- launch ----------------
extern "C" void kernel_launch(void* const* d_in, const int* in_sizes, int n_in,
                              void* d_out, int out_size)
{
    const float* x       = (const float*)d_in[0];
    const float* conv1_w = (const float*)d_in[1];
    const float* conv1_b = (const float*)d_in[2];
    const float* conv2_w = (const float*)d_in[3];
    const float* conv2_b = (const float*)d_in[4];
    const float* fc1_w   = (const float*)d_in[5];
    const float* fc1_b   = (const float*)d_in[6];
    const float* fc2_w   = (const float*)d_in[7];
    const float* fc2_b   = (const float*)d_in[8];
    const float* fc3_w   = (const float*)d_in[9];
    const float* fc3_b   = (const float*)d_in[10];
    const float* pl_w    = (const float*)d_in[11];
    const float* pl_b    = (const float*)d_in[12];
    const float* pl_scale= (const float*)d_in[13];
    const float* pl_bias = (const float*)d_in[14];
    float* out = (float*)d_out;

    conv1_kernel<<<dim3(2, 18, BATCH), dim3(16, 8)>>>(x, conv1_w, conv1_b);
    conv2_kernel<<<dim3(1, 9, BATCH), dim3(16, 8)>>>(conv2_w, conv2_b);
    fc1_kernel<<<dim3(4, KSPLIT), 256>>>(fc1_w);
    head_kernel<<<BATCH, 128>>>(fc1_b, fc2_w, fc2_b, fc3_w, fc3_b,
                                pl_w, pl_b, pl_scale, pl_bias);
    graph_kernel<<<BATCH, 256>>>(out);
}